// round 11
// baseline (speedup 1.0000x reference)
#include <cuda_runtime.h>

#define N_PTS   8192
#define C_DIM   64
#define C4      (C_DIM/4)
#define NQ      (3*N_PTS)                 // 24576 queries
#define VOFF    ((size_t)4*N_PTS*C_DIM)   // float offset of out_coords

#define G       64
#define NCELL   (G*G)                     // 4096 cells
#define HC      0.015625f                 // 1/64, exact in fp32

#define TPB     256

typedef unsigned long long u64;
typedef unsigned int       u32;

// Grid acceleration structure (rebuilt every launch; replay-deterministic).
__device__ int    g_cnt[NCELL];
__device__ int    g_start[NCELL + 1];
__device__ int    g_cur[NCELL];
__device__ float4 g_pts[N_PTS];           // (x, y, |c|^2, idx bits)

// ---------------------------------------------------------------------------
// K1: zero histogram + copy original values + build all 4N coordinate rows.
// Items: [0,131072) value float4s, [131072,135168) g_cnt zero,
//        [135168,143360) coordinate points.  Grid = 560 CTAs.
// ---------------------------------------------------------------------------
__global__ void __launch_bounds__(TPB)
k1_init(const float4* __restrict__ val4,
        const float2* __restrict__ c2,
        const float*  __restrict__ spacing,
        float*        __restrict__ out)
{
    const int t = blockIdx.x * TPB + threadIdx.x;

    if (t < N_PTS * C4) {
        reinterpret_cast<float4*>(out)[t] = __ldg(&val4[t]);
    } else if (t < N_PTS * C4 + NCELL) {
        g_cnt[t - N_PTS * C4] = 0;
    } else if (t < N_PTS * C4 + NCELL + N_PTS) {
        int i = t - (N_PTS * C4 + NCELL);
        float2 c = __ldg(&c2[i]);
        float s0 = __ldg(&spacing[0]);
        float s1 = __ldg(&spacing[1]);
        float xs = __fadd_rn(c.x, s0);
        float ys = __fadd_rn(c.y, s1);
        float2* outc = reinterpret_cast<float2*>(out + VOFF);
        outc[i]             = c;
        outc[N_PTS   + i]   = make_float2(xs,  ys);
        outc[2*N_PTS + i]   = make_float2(c.x, ys);
        outc[3*N_PTS + i]   = make_float2(xs,  c.y);
    }
}

__device__ __forceinline__ int clamp_cell(float v) {
    int c = (int)floorf(v * 64.0f);
    return min(max(c, 0), G - 1);
}

// ---------------------------------------------------------------------------
// K2: histogram points into cells.  Grid = 32 CTAs.
// ---------------------------------------------------------------------------
__global__ void __launch_bounds__(TPB)
k2_hist(const float2* __restrict__ c2)
{
    const int i = blockIdx.x * TPB + threadIdx.x;   // 0..8191
    float2 c = __ldg(&c2[i]);
    int cell = clamp_cell(c.y) * G + clamp_cell(c.x);
    atomicAdd(&g_cnt[cell], 1);
}

// ---------------------------------------------------------------------------
// K3: exclusive prefix sum over 4096 cell counts.  One CTA of 1024 threads,
// 4 cells per thread; warp shuffle scan + cross-warp scan.
// ---------------------------------------------------------------------------
__global__ void __launch_bounds__(1024)
k3_prefix()
{
    __shared__ int wsum[32];
    const int t = threadIdx.x;
    const int c = t * 4;

    int v0 = g_cnt[c], v1 = g_cnt[c+1], v2 = g_cnt[c+2], v3 = g_cnt[c+3];
    int s  = v0 + v1 + v2 + v3;

    const int lane = t & 31, wid = t >> 5;
    int inc = s;
    #pragma unroll
    for (int o = 1; o < 32; o <<= 1) {
        int n = __shfl_up_sync(0xffffffffu, inc, o);
        if (lane >= o) inc += n;
    }
    if (lane == 31) wsum[wid] = inc;
    __syncthreads();
    if (wid == 0) {
        int w = wsum[lane];
        #pragma unroll
        for (int o = 1; o < 32; o <<= 1) {
            int n = __shfl_up_sync(0xffffffffu, w, o);
            if (lane >= o) w += n;
        }
        wsum[lane] = w;
    }
    __syncthreads();

    int base = (wid ? wsum[wid - 1] : 0) + (inc - s);
    g_start[c]     = base;                 g_cur[c]     = base;
    g_start[c + 1] = base + v0;            g_cur[c + 1] = base + v0;
    g_start[c + 2] = base + v0 + v1;       g_cur[c + 2] = base + v0 + v1;
    g_start[c + 3] = base + v0 + v1 + v2;  g_cur[c + 3] = base + v0 + v1 + v2;
    if (t == 1023) g_start[NCELL] = base + s;   // = N_PTS
}

// ---------------------------------------------------------------------------
// K4: scatter points into cell-sorted array.  Order within a cell is
// nondeterministic, but all downstream reductions are set-based (lexi-min),
// so the final output is deterministic.  Grid = 32 CTAs.
// ---------------------------------------------------------------------------
__global__ void __launch_bounds__(TPB)
k4_scatter(const float2* __restrict__ c2)
{
    const int i = blockIdx.x * TPB + threadIdx.x;   // 0..8191
    float2 c = __ldg(&c2[i]);
    int cell = clamp_cell(c.y) * G + clamp_cell(c.x);
    float sc = __fadd_rn(__fmul_rn(c.x, c.x), __fmul_rn(c.y, c.y));
    int pos = atomicAdd(&g_cur[cell], 1);
    g_pts[pos] = make_float4(c.x, c.y, sc, __int_as_float(i));
}

// ---------------------------------------------------------------------------
// K5: ring-search nearest neighbor (exact, bit-identical d2 + lexicographic
// (d, idx) tie semantics) + coalesced value-row gather.
// Grid = NQ/TPB = 96 CTAs, one query per thread.
// ---------------------------------------------------------------------------
__global__ void __launch_bounds__(TPB)
k5_query(const float2* __restrict__ c2,
         const float*  __restrict__ spacing,
         const float*  __restrict__ shift,
         const float4* __restrict__ val4,
         float*        __restrict__ out)
{
    __shared__ int s_start[NCELL + 1];
    __shared__ int sidx[TPB];

    for (int t = threadIdx.x; t < NCELL + 1; t += TPB)
        s_start[t] = g_start[t];
    __syncthreads();

    const int q = blockIdx.x * TPB + threadIdx.x;   // 0..24575
    const int g = q >> 13;
    const int i = q & (N_PTS - 1);

    float2 c  = __ldg(&c2[i]);
    float s0  = __ldg(&spacing[0]), s1  = __ldg(&spacing[1]);
    float sh0 = __ldg(&shift[0]),   sh1 = __ldg(&shift[1]);

    float nc0, nc1;
    if (g == 0)      { nc0 = __fadd_rn(c.x, s0); nc1 = __fadd_rn(c.y, s1); }
    else if (g == 1) { nc0 = c.x;                nc1 = __fadd_rn(c.y, s1); }
    else             { nc0 = __fadd_rn(c.x, s0); nc1 = c.y;                }

    const float a0 = __fsub_rn(nc0, sh0);
    const float a1 = __fsub_rn(nc1, sh1);
    const float sa = __fadd_rn(__fmul_rn(a0, a0), __fmul_rn(a1, a1));

    const int cx = clamp_cell(a0);
    const int cy = clamp_cell(a1);

    float bestd = __int_as_float(0x7f800000);   // +inf
    u64   bestk = ~0ull;

    // Exact per-pair semantics (verified bit-identical to reference):
    //   m = fma(a1, py, RN(a0*px));  d = fma(m, -2, RN(sa+sc))
    #define SCAN_CELL(CELL) do {                                            \
        int s_ = s_start[(CELL)], e_ = s_start[(CELL) + 1];                 \
        for (int k_ = s_; k_ < e_; k_++) {                                  \
            float4 p_ = g_pts[k_];                                          \
            float m_ = __fmaf_rn(a1, p_.y, __fmul_rn(a0, p_.x));            \
            float d_ = __fmaf_rn(m_, -2.0f, __fadd_rn(sa, p_.z));           \
            u32 ub_ = __float_as_uint(d_);                                  \
            ub_ = (ub_ & 0x80000000u) ? ~ub_ : (ub_ | 0x80000000u);         \
            u64 key_ = ((u64)ub_ << 32) | (u32)__float_as_uint(p_.w);       \
            bestk = (key_ < bestk) ? key_ : bestk;                          \
            bestd = fminf(bestd, d_);                                       \
        }                                                                   \
    } while (0)

    #pragma unroll 1
    for (int r = 0; r <= G; r++) {
        const int x0 = max(cx - r, 0), x1 = min(cx + r, G - 1);
        const int y0 = max(cy - r, 0), y1 = min(cy + r, G - 1);

        #pragma unroll 1
        for (int y = y0; y <= y1; y++) {
            if (y == cy - r || y == cy + r) {
                #pragma unroll 1
                for (int x = x0; x <= x1; x++) SCAN_CELL(y * G + x);
            } else {
                if (cx - r >= 0)     SCAN_CELL(y * G + (cx - r));
                if (cx + r <= G - 1) SCAN_CELL(y * G + (cx + r));
            }
        }

        // Lower bound on TRUE distance from a to any unscanned point:
        // min over grid-interior sides of the scanned square.
        float lb = __int_as_float(0x7f800000);
        if (cx - r > 0)     lb = fminf(lb, __fsub_rn(a0, (float)(cx - r) * HC));
        if (cx + r < G - 1) lb = fminf(lb, __fsub_rn((float)(cx + r + 1) * HC, a0));
        if (cy - r > 0)     lb = fminf(lb, __fsub_rn(a1, (float)(cy - r) * HC));
        if (cy + r < G - 1) lb = fminf(lb, __fsub_rn((float)(cy + r + 1) * HC, a1));

        if (lb > 1e9f) break;                               // grid fully scanned
        if (__fmul_rn(lb, lb) > bestd + 1e-4f) break;       // margin >> 5e-6 fp slack
    }
    #undef SCAN_CELL

    sidx[threadIdx.x] = (int)(u32)(bestk & 0xFFFFFFFFull);
    __syncthreads();

    // Coalesced gather: 256 winner rows per CTA.
    const int qbase = blockIdx.x * TPB;
    float4* outv4 = reinterpret_cast<float4*>(out);
    #pragma unroll
    for (int t = threadIdx.x; t < TPB * C4; t += TPB) {
        int rr  = t >> 4;
        int ccx = t & (C4 - 1);
        outv4[(size_t)(N_PTS + qbase + rr) * C4 + ccx] =
            __ldg(&val4[(size_t)sidx[rr] * C4 + ccx]);
    }
}

// ---------------------------------------------------------------------------
extern "C" void kernel_launch(void* const* d_in, const int* in_sizes, int n_in,
                              void* d_out, int out_size)
{
    const float4* val4    = (const float4*)d_in[0];
    const float2* c2      = (const float2*)d_in[1];
    const float*  spacing = (const float*) d_in[2];
    const float*  shift   = (const float*) d_in[3];
    float* out = (float*)d_out;

    k1_init<<<(N_PTS * C4 + NCELL + N_PTS) / TPB, TPB>>>(val4, c2, spacing, out);
    k2_hist<<<N_PTS / TPB, TPB>>>(c2);
    k3_prefix<<<1, 1024>>>();
    k4_scatter<<<N_PTS / TPB, TPB>>>(c2);
    k5_query<<<NQ / TPB, TPB>>>(c2, spacing, shift, val4, out);
}

// round 12
// speedup vs baseline: 56.6603x; 56.6603x over previous
#include <cuda_runtime.h>

#define N_PTS   8192
#define C_DIM   64
#define C4      (C_DIM/4)
#define NQ      (3*N_PTS)                 // 24576 queries
#define VOFF    ((size_t)4*N_PTS*C_DIM)   // float offset of out_coords

#define G       64
#define NCELL   (G*G)                     // 4096 cells
#define HC      0.015625f                 // 1/64, exact in fp32

#define TPB     256

typedef unsigned long long u64;
typedef unsigned int       u32;

// Grid acceleration structure (rebuilt every launch; replay-deterministic).
__device__ int    g_cnt[NCELL];
__device__ int    g_start[NCELL + 1];
__device__ int    g_cur[NCELL];
__device__ float4 g_pts[N_PTS];           // (x, y, |c|^2, idx bits)

// ---------------------------------------------------------------------------
// K1: zero histogram + copy original values + build all 4N coordinate rows.
// ---------------------------------------------------------------------------
__global__ void __launch_bounds__(TPB)
k1_init(const float4* __restrict__ val4,
        const float2* __restrict__ c2,
        const float*  __restrict__ spacing,
        float*        __restrict__ out)
{
    const int t = blockIdx.x * TPB + threadIdx.x;

    if (t < N_PTS * C4) {
        reinterpret_cast<float4*>(out)[t] = __ldg(&val4[t]);
    } else if (t < N_PTS * C4 + NCELL) {
        g_cnt[t - N_PTS * C4] = 0;
    } else if (t < N_PTS * C4 + NCELL + N_PTS) {
        int i = t - (N_PTS * C4 + NCELL);
        float2 c = __ldg(&c2[i]);
        float s0 = __ldg(&spacing[0]);
        float s1 = __ldg(&spacing[1]);
        float xs = __fadd_rn(c.x, s0);
        float ys = __fadd_rn(c.y, s1);
        float2* outc = reinterpret_cast<float2*>(out + VOFF);
        outc[i]             = c;
        outc[N_PTS   + i]   = make_float2(xs,  ys);
        outc[2*N_PTS + i]   = make_float2(c.x, ys);
        outc[3*N_PTS + i]   = make_float2(xs,  c.y);
    }
}

__device__ __forceinline__ int clamp_cell(float v) {
    int c = (int)floorf(v * 64.0f);
    return min(max(c, 0), G - 1);
}

// ---------------------------------------------------------------------------
// K2: histogram points into cells.
// ---------------------------------------------------------------------------
__global__ void __launch_bounds__(TPB)
k2_hist(const float2* __restrict__ c2)
{
    const int i = blockIdx.x * TPB + threadIdx.x;   // 0..8191
    float2 c = __ldg(&c2[i]);
    int cell = clamp_cell(c.y) * G + clamp_cell(c.x);
    atomicAdd(&g_cnt[cell], 1);
}

// ---------------------------------------------------------------------------
// K3: exclusive prefix sum over 4096 cell counts (1 CTA, 1024 threads).
// ---------------------------------------------------------------------------
__global__ void __launch_bounds__(1024)
k3_prefix()
{
    __shared__ int wsum[32];
    const int t = threadIdx.x;
    const int c = t * 4;

    int v0 = g_cnt[c], v1 = g_cnt[c+1], v2 = g_cnt[c+2], v3 = g_cnt[c+3];
    int s  = v0 + v1 + v2 + v3;

    const int lane = t & 31, wid = t >> 5;
    int inc = s;
    #pragma unroll
    for (int o = 1; o < 32; o <<= 1) {
        int n = __shfl_up_sync(0xffffffffu, inc, o);
        if (lane >= o) inc += n;
    }
    if (lane == 31) wsum[wid] = inc;
    __syncthreads();
    if (wid == 0) {
        int w = wsum[lane];
        #pragma unroll
        for (int o = 1; o < 32; o <<= 1) {
            int n = __shfl_up_sync(0xffffffffu, w, o);
            if (lane >= o) w += n;
        }
        wsum[lane] = w;
    }
    __syncthreads();

    int base = (wid ? wsum[wid - 1] : 0) + (inc - s);
    g_start[c]     = base;                 g_cur[c]     = base;
    g_start[c + 1] = base + v0;            g_cur[c + 1] = base + v0;
    g_start[c + 2] = base + v0 + v1;       g_cur[c + 2] = base + v0 + v1;
    g_start[c + 3] = base + v0 + v1 + v2;  g_cur[c + 3] = base + v0 + v1 + v2;
    if (t == 1023) g_start[NCELL] = base + s;   // = N_PTS
}

// ---------------------------------------------------------------------------
// K4: scatter points into cell-sorted array. Intra-cell order is
// nondeterministic but downstream reduction is a set-min -> deterministic.
// ---------------------------------------------------------------------------
__global__ void __launch_bounds__(TPB)
k4_scatter(const float2* __restrict__ c2)
{
    const int i = blockIdx.x * TPB + threadIdx.x;   // 0..8191
    float2 c = __ldg(&c2[i]);
    int cell = clamp_cell(c.y) * G + clamp_cell(c.x);
    float sc = __fadd_rn(__fmul_rn(c.x, c.x), __fmul_rn(c.y, c.y));
    int pos = atomicAdd(&g_cur[cell], 1);
    g_pts[pos] = make_float4(c.x, c.y, sc, __int_as_float(i));
}

// ---------------------------------------------------------------------------
// K5: ring-search NN (exact, bit-identical d2 + lexicographic (d, idx)
// semantics) + coalesced value-row gather. One query per thread.
//
// Termination lower bound (fixed from R11): unscanned points live in
// ([0,1]^2) minus the scanned square. For each remaining side-slab the true
// distance^2 is at least (axis gap)^2 + (query clearance to [0,1] in the
// OTHER axis)^2 -- the second term is what makes outside-domain queries
// (shifted coords up to ~2) terminate after ring 0-1 instead of scanning
// the whole grid.
// ---------------------------------------------------------------------------
__global__ void __launch_bounds__(TPB)
k5_query(const float2* __restrict__ c2,
         const float*  __restrict__ spacing,
         const float*  __restrict__ shift,
         const float4* __restrict__ val4,
         float*        __restrict__ out)
{
    __shared__ int s_start[NCELL + 1];
    __shared__ int sidx[TPB];

    for (int t = threadIdx.x; t < NCELL + 1; t += TPB)
        s_start[t] = g_start[t];
    __syncthreads();

    const int q = blockIdx.x * TPB + threadIdx.x;   // 0..24575
    const int g = q >> 13;
    const int i = q & (N_PTS - 1);

    float2 c  = __ldg(&c2[i]);
    float s0  = __ldg(&spacing[0]), s1  = __ldg(&spacing[1]);
    float sh0 = __ldg(&shift[0]),   sh1 = __ldg(&shift[1]);

    float nc0, nc1;
    if (g == 0)      { nc0 = __fadd_rn(c.x, s0); nc1 = __fadd_rn(c.y, s1); }
    else if (g == 1) { nc0 = c.x;                nc1 = __fadd_rn(c.y, s1); }
    else             { nc0 = __fadd_rn(c.x, s0); nc1 = c.y;                }

    const float a0 = __fsub_rn(nc0, sh0);
    const float a1 = __fsub_rn(nc1, sh1);
    const float sa = __fadd_rn(__fmul_rn(a0, a0), __fmul_rn(a1, a1));

    const int cx = clamp_cell(a0);
    const int cy = clamp_cell(a1);

    // Query clearance to the point domain [0,1] per axis.
    const float dxo = fmaxf(fmaxf(a0 - 1.0f, -a0), 0.0f);
    const float dyo = fmaxf(fmaxf(a1 - 1.0f, -a1), 0.0f);
    const float dxo2 = dxo * dxo;
    const float dyo2 = dyo * dyo;

    float bestd = __int_as_float(0x7f800000);   // +inf
    u64   bestk = ~0ull;

    // Exact per-pair semantics (verified bit-identical to reference):
    //   m = fma(a1, py, RN(a0*px));  d = fma(m, -2, RN(sa+sc))
    #define SCAN_CELL(CELL) do {                                            \
        int s_ = s_start[(CELL)], e_ = s_start[(CELL) + 1];                 \
        for (int k_ = s_; k_ < e_; k_++) {                                  \
            float4 p_ = g_pts[k_];                                          \
            float m_ = __fmaf_rn(a1, p_.y, __fmul_rn(a0, p_.x));            \
            float d_ = __fmaf_rn(m_, -2.0f, __fadd_rn(sa, p_.z));           \
            u32 ub_ = __float_as_uint(d_);                                  \
            ub_ = (ub_ & 0x80000000u) ? ~ub_ : (ub_ | 0x80000000u);         \
            u64 key_ = ((u64)ub_ << 32) | (u32)__float_as_uint(p_.w);       \
            bestk = (key_ < bestk) ? key_ : bestk;                          \
            bestd = fminf(bestd, d_);                                       \
        }                                                                   \
    } while (0)

    #pragma unroll 1
    for (int r = 0; r <= G; r++) {
        const int x0 = max(cx - r, 0), x1 = min(cx + r, G - 1);
        const int y0 = max(cy - r, 0), y1 = min(cy + r, G - 1);

        #pragma unroll 1
        for (int y = y0; y <= y1; y++) {
            if (y == cy - r || y == cy + r) {
                #pragma unroll 1
                for (int x = x0; x <= x1; x++) SCAN_CELL(y * G + x);
            } else {
                if (cx - r >= 0)     SCAN_CELL(y * G + (cx - r));
                if (cx + r <= G - 1) SCAN_CELL(y * G + (cx + r));
            }
        }

        // lb^2 to the unscanned region (each side slab, 2D-correct).
        float lb2 = __int_as_float(0x7f800000);
        if (x0 > 0) {
            float dx = fmaxf(__fsub_rn(a0, (float)x0 * HC), 0.0f);
            lb2 = fminf(lb2, __fmaf_rn(dx, dx, dyo2));
        }
        if (x1 < G - 1) {
            float dx = fmaxf(__fsub_rn((float)(x1 + 1) * HC, a0), 0.0f);
            lb2 = fminf(lb2, __fmaf_rn(dx, dx, dyo2));
        }
        if (y0 > 0) {
            float dy = fmaxf(__fsub_rn(a1, (float)y0 * HC), 0.0f);
            lb2 = fminf(lb2, __fmaf_rn(dy, dy, dxo2));
        }
        if (y1 < G - 1) {
            float dy = fmaxf(__fsub_rn((float)(y1 + 1) * HC, a1), 0.0f);
            lb2 = fminf(lb2, __fmaf_rn(dy, dy, dxo2));
        }

        if (lb2 > 1e18f) break;                 // whole grid scanned
        if (lb2 > bestd + 1e-4f) break;         // margin >> fp slack (~1e-6)
    }
    #undef SCAN_CELL

    sidx[threadIdx.x] = (int)(u32)(bestk & 0xFFFFFFFFull);
    __syncthreads();

    // Coalesced gather: 256 winner rows per CTA.
    const int qbase = blockIdx.x * TPB;
    float4* outv4 = reinterpret_cast<float4*>(out);
    #pragma unroll
    for (int t = threadIdx.x; t < TPB * C4; t += TPB) {
        int rr  = t >> 4;
        int ccx = t & (C4 - 1);
        outv4[(size_t)(N_PTS + qbase + rr) * C4 + ccx] =
            __ldg(&val4[(size_t)sidx[rr] * C4 + ccx]);
    }
}

// ---------------------------------------------------------------------------
extern "C" void kernel_launch(void* const* d_in, const int* in_sizes, int n_in,
                              void* d_out, int out_size)
{
    const float4* val4    = (const float4*)d_in[0];
    const float2* c2      = (const float2*)d_in[1];
    const float*  spacing = (const float*) d_in[2];
    const float*  shift   = (const float*) d_in[3];
    float* out = (float*)d_out;

    k1_init<<<(N_PTS * C4 + NCELL + N_PTS) / TPB, TPB>>>(val4, c2, spacing, out);
    k2_hist<<<N_PTS / TPB, TPB>>>(c2);
    k3_prefix<<<1, 1024>>>();
    k4_scatter<<<N_PTS / TPB, TPB>>>(c2);
    k5_query<<<NQ / TPB, TPB>>>(c2, spacing, shift, val4, out);
}

// round 13
// speedup vs baseline: 95.9479x; 1.6934x over previous
#include <cuda_runtime.h>

#define N_PTS   8192
#define C_DIM   64
#define C4      (C_DIM/4)
#define NQ      (3*N_PTS)                 // 24576 queries
#define VOFF    ((size_t)4*N_PTS*C_DIM)   // float offset of out_coords

#define G       64
#define NCELL   (G*G)                     // 4096 cells
#define HC      0.015625f                 // 1/64, exact in fp32

#define TPB     256
#define BIN_CTAS 32
#define QW_CTAS (NQ/8)                    // 3072 CTAs, 8 warp-queries each
#define ITEMS   46                        // copy items per query CTA
#define FULL    0xffffffffu

typedef unsigned long long u64;
typedef unsigned int       u32;

// Grid acceleration structure (rebuilt every launch; replay-deterministic).
__device__ int    g_cnt[NCELL];
__device__ int    g_start[NCELL + 1];
__device__ int    g_cur[NCELL];
__device__ float4 g_pts[N_PTS];           // (x, y, |c|^2, idx bits)

// Grid-barrier counters for the binning kernel (reset each use).
__device__ volatile int g_arr[3];
__device__ int          g_dep[3];

__device__ __forceinline__ int clamp_cell(float v) {
    int c = (int)floorf(v * 64.0f);
    return min(max(c, 0), G - 1);
}

// R9-verified replay-safe grid barrier (all BIN_CTAS co-resident).
__device__ __forceinline__ void gbar(int b) {
    __syncthreads();
    if (threadIdx.x == 0) {
        __threadfence();
        atomicAdd((int*)&g_arr[b], 1);
        while (g_arr[b] != BIN_CTAS) __nanosleep(32);
        int p = atomicAdd(&g_dep[b], 1);
        if (p == BIN_CTAS - 1) {
            g_dep[b] = 0;
            __threadfence();
            *(int*)&g_arr[b] = 0;
        }
    }
    __syncthreads();
}

// ---------------------------------------------------------------------------
// K_bin: zero -> histogram -> prefix scan (CTA 0) -> scatter, one kernel.
// 32 CTAs x 256 threads = 8192 threads, one point each.
// ---------------------------------------------------------------------------
__global__ void __launch_bounds__(TPB)
k_bin(const float2* __restrict__ c2)
{
    const int gi = blockIdx.x * TPB + threadIdx.x;   // 0..8191

    // phase 0: zero the histogram
    if (gi < NCELL) g_cnt[gi] = 0;
    gbar(0);

    // phase 1: histogram
    float2 c = __ldg(&c2[gi]);
    const int cell = clamp_cell(c.y) * G + clamp_cell(c.x);
    atomicAdd(&g_cnt[cell], 1);
    gbar(1);

    // phase 2: exclusive prefix scan over 4096 cells (CTA 0 only)
    if (blockIdx.x == 0) {
        __shared__ int wsum[8];
        const int t = threadIdx.x;
        const int lane = t & 31, w = t >> 5;
        int v[16], s = 0;
        #pragma unroll
        for (int k = 0; k < 16; k++) {
            v[k] = __ldcg(&g_cnt[t * 16 + k]);
            s += v[k];
        }
        int inc = s;
        #pragma unroll
        for (int o = 1; o < 32; o <<= 1) {
            int n = __shfl_up_sync(FULL, inc, o);
            if (lane >= o) inc += n;
        }
        if (lane == 31) wsum[w] = inc;
        __syncthreads();
        if (t < 8) {
            int x = wsum[t];
            #pragma unroll
            for (int o = 1; o < 8; o <<= 1) {
                int n = __shfl_up_sync(0xffu, x, o);
                if (t >= o) x += n;
            }
            wsum[t] = x;
        }
        __syncthreads();
        int run = (inc - s) + (w ? wsum[w - 1] : 0);
        #pragma unroll
        for (int k = 0; k < 16; k++) {
            g_start[t * 16 + k] = run;
            g_cur[t * 16 + k]   = run;
            run += v[k];
        }
        if (t == 255) g_start[NCELL] = run;     // = N_PTS
    }
    gbar(2);

    // phase 3: scatter point into cell-sorted array (intra-cell order is
    // nondeterministic; downstream reduction is a set-min -> deterministic).
    float sc = __fadd_rn(__fmul_rn(c.x, c.x), __fmul_rn(c.y, c.y));
    int pos = atomicAdd(&g_cur[cell], 1);
    g_pts[pos] = make_float4(c.x, c.y, sc, __int_as_float(gi));
}

// ---------------------------------------------------------------------------
// K_query: warp-per-query exact NN (bit-identical d2, lexicographic (d, idx)
// tie semantics) + output copies + coalesced value-row gather.
// Grid = 3072 CTAs x 256 threads; warp w of CTA b owns query b*8+w.
// ---------------------------------------------------------------------------
__global__ void __launch_bounds__(TPB)
k_query(const float2* __restrict__ c2,
        const float*  __restrict__ spacing,
        const float*  __restrict__ shift,
        const float4* __restrict__ val4,
        float*        __restrict__ out)
{
    __shared__ int widx[8];
    const int lane = threadIdx.x & 31;
    const int wid  = threadIdx.x >> 5;

    // ---- distributed output copies (independent of binning results) ----
    float s0 = __ldg(&spacing[0]), s1 = __ldg(&spacing[1]);
    if (threadIdx.x < ITEMS) {
        int item = blockIdx.x * ITEMS + threadIdx.x;
        if (item < N_PTS * C4) {
            reinterpret_cast<float4*>(out)[item] = __ldg(&val4[item]);
        } else if (item < N_PTS * C4 + N_PTS) {
            int i = item - N_PTS * C4;
            float2 cc = __ldg(&c2[i]);
            float xs = __fadd_rn(cc.x, s0);
            float ys = __fadd_rn(cc.y, s1);
            float2* outc = reinterpret_cast<float2*>(out + VOFF);
            outc[i]             = cc;
            outc[N_PTS   + i]   = make_float2(xs,   ys);
            outc[2*N_PTS + i]   = make_float2(cc.x, ys);
            outc[3*N_PTS + i]   = make_float2(xs,   cc.y);
        }
    }

    // ---- per-warp query setup (uniform across the warp) ----
    const int q = blockIdx.x * 8 + wid;      // 0..24575
    const int g = q >> 13;
    const int i = q & (N_PTS - 1);

    float2 c  = __ldg(&c2[i]);
    float sh0 = __ldg(&shift[0]), sh1 = __ldg(&shift[1]);

    float nc0, nc1;
    if (g == 0)      { nc0 = __fadd_rn(c.x, s0); nc1 = __fadd_rn(c.y, s1); }
    else if (g == 1) { nc0 = c.x;                nc1 = __fadd_rn(c.y, s1); }
    else             { nc0 = __fadd_rn(c.x, s0); nc1 = c.y;                }

    const float a0 = __fsub_rn(nc0, sh0);
    const float a1 = __fsub_rn(nc1, sh1);
    const float sa = __fadd_rn(__fmul_rn(a0, a0), __fmul_rn(a1, a1));

    const int cx = clamp_cell(a0);
    const int cy = clamp_cell(a1);

    // query clearance to the point domain [0,1] per axis
    const float dxo = fmaxf(fmaxf(a0 - 1.0f, -a0), 0.0f);
    const float dyo = fmaxf(fmaxf(a1 - 1.0f, -a1), 0.0f);
    const float dxo2 = dxo * dxo;
    const float dyo2 = dyo * dyo;

    u64 bestk = ~0ull;

    // ---- expanding-square scan (r = 1, 3, 7, ... ; rescans are harmless) --
    int r = 1;
    while (true) {
        const int x0 = max(cx - r, 0), x1 = min(cx + r, G - 1);
        const int y0 = max(cy - r, 0), y1 = min(cy + r, G - 1);
        const int w = x1 - x0 + 1;
        const int ncell = w * (y1 - y0 + 1);

        for (int base = 0; base < ncell; base += 32) {
            const int cl = base + lane;
            int s = 0, cnt = 0;
            if (cl < ncell) {
                int cell = (y0 + cl / w) * G + x0 + cl % w;
                s   = __ldg(&g_start[cell]);
                cnt = __ldg(&g_start[cell + 1]) - s;
            }
            // warp exclusive scan of counts
            int inc = cnt;
            #pragma unroll
            for (int o = 1; o < 32; o <<= 1) {
                int n = __shfl_up_sync(FULL, inc, o);
                if (lane >= o) inc += n;
            }
            const int excl  = inc - cnt;
            const int total = __shfl_sync(FULL, inc, 31);

            for (int t0 = 0; t0 < total; t0 += 32) {
                const int t = t0 + lane;
                // 5-step warp binary search: largest j with excl[j] <= t
                int j = 0;
                #pragma unroll
                for (int st = 16; st; st >>= 1) {
                    int cd = j + st;
                    int ec = __shfl_sync(FULL, excl, cd);
                    if (ec <= t) j = cd;
                }
                int sj = __shfl_sync(FULL, s, j);
                int ej = __shfl_sync(FULL, excl, j);
                if (t < total) {
                    float4 p = __ldg(&g_pts[sj + (t - ej)]);
                    // exact per-pair semantics (verified bit-identical):
                    //   m = fma(a1, py, RN(a0*px));  d = fma(m, -2, RN(sa+sc))
                    float m = __fmaf_rn(a1, p.y, __fmul_rn(a0, p.x));
                    float d = __fmaf_rn(m, -2.0f, __fadd_rn(sa, p.z));
                    u32 ub = __float_as_uint(d);
                    ub = (ub & 0x80000000u) ? ~ub : (ub | 0x80000000u);
                    u64 key = ((u64)ub << 32) | (u32)__float_as_uint(p.w);
                    bestk = (key < bestk) ? key : bestk;
                }
            }
        }

        // lb^2 to the unscanned region: per side-slab, (axis gap)^2 +
        // (query clearance to [0,1] in the other axis)^2.
        float lb2 = __int_as_float(0x7f800000);
        if (x0 > 0) {
            float dx = fmaxf(__fsub_rn(a0, (float)x0 * HC), 0.0f);
            lb2 = fminf(lb2, __fmaf_rn(dx, dx, dyo2));
        }
        if (x1 < G - 1) {
            float dx = fmaxf(__fsub_rn((float)(x1 + 1) * HC, a0), 0.0f);
            lb2 = fminf(lb2, __fmaf_rn(dx, dx, dyo2));
        }
        if (y0 > 0) {
            float dy = fmaxf(__fsub_rn(a1, (float)y0 * HC), 0.0f);
            lb2 = fminf(lb2, __fmaf_rn(dy, dy, dxo2));
        }
        if (y1 < G - 1) {
            float dy = fmaxf(__fsub_rn((float)(y1 + 1) * HC, a1), 0.0f);
            lb2 = fminf(lb2, __fmaf_rn(dy, dy, dxo2));
        }

        if (lb2 > 1e18f) break;                 // whole grid scanned

        // warp-wide current best distance (NaN if nothing found -> continue)
        u32 mu = __reduce_min_sync(FULL, (u32)(bestk >> 32));
        float bd = (mu & 0x80000000u) ? __uint_as_float(mu & 0x7fffffffu)
                                      : __uint_as_float(~mu);
        if (lb2 > bd + 1e-4f) break;            // margin >> fp slack (~1e-6)
        r = 2 * r + 1;
    }

    // ---- final lexicographic (d, idx) warp reduction ----
    {
        u32 bub = (u32)(bestk >> 32);
        u32 mu  = __reduce_min_sync(FULL, bub);
        u32 cnd = (bub == mu) ? (u32)bestk : 0xffffffffu;
        u32 mix = __reduce_min_sync(FULL, cnd);
        if (lane == 0) widx[wid] = (int)mix;
    }
    __syncthreads();

    // ---- coalesced gather: 8 winner rows per CTA ----
    if (threadIdx.x < 8 * C4) {
        int rr  = threadIdx.x >> 4;
        int ccx = threadIdx.x & (C4 - 1);
        int row = blockIdx.x * 8 + rr;
        reinterpret_cast<float4*>(out)[(size_t)(N_PTS + row) * C4 + ccx] =
            __ldg(&val4[(size_t)widx[rr] * C4 + ccx]);
    }
}

// ---------------------------------------------------------------------------
extern "C" void kernel_launch(void* const* d_in, const int* in_sizes, int n_in,
                              void* d_out, int out_size)
{
    const float4* val4    = (const float4*)d_in[0];
    const float2* c2      = (const float2*)d_in[1];
    const float*  spacing = (const float*) d_in[2];
    const float*  shift   = (const float*) d_in[3];
    float* out = (float*)d_out;

    k_bin<<<BIN_CTAS, TPB>>>(c2);
    k_query<<<QW_CTAS, TPB>>>(c2, spacing, shift, val4, out);
}

// round 14
// speedup vs baseline: 114.1564x; 1.1898x over previous
#include <cuda_runtime.h>

#define N_PTS   8192
#define C_DIM   64
#define C4      (C_DIM/4)
#define NQ      (3*N_PTS)                 // 24576 queries
#define VOFF    ((size_t)4*N_PTS*C_DIM)   // float offset of out_coords

#define G       64
#define NCELL   (G*G)                     // 4096 cells
#define HC      0.015625f                 // 1/64, exact in fp32
#define CAP     16                        // bucket capacity per cell

#define TPB      256
#define BIN_CTAS 32
#define QPC      16                       // queries per CTA (2 per warp)
#define QW_CTAS  (NQ/QPC)                 // 1536 CTAs
#define NITEM    (N_PTS*C4 + N_PTS)       // 139264 copy items
#define ITEMS    91                       // ceil(NITEM / QW_CTAS)
#define FULL     0xffffffffu

typedef unsigned long long u64;
typedef unsigned int       u32;

// Bucketed grid (rebuilt every launch; replay-deterministic).
__device__ int    g_bcnt[NCELL];
__device__ float4 g_pts[NCELL * CAP];     // (x, y, |c|^2, idx bits)
__device__ int    g_ovfcnt;
__device__ float4 g_ovf[N_PTS];           // overflow (normally empty)

// Grid-barrier counters (reset each use; replay-safe).
__device__ volatile int g_arr;
__device__ int          g_dep;

__device__ __forceinline__ int clamp_cell(float v) {
    int c = (int)floorf(v * 64.0f);
    return min(max(c, 0), G - 1);
}

// ---------------------------------------------------------------------------
// K_bin: zero counters -> barrier -> bucket scatter. 32 CTAs, 1 pt/thread.
// Intra-cell order nondeterministic; downstream reduction is a set-min.
// ---------------------------------------------------------------------------
__global__ void __launch_bounds__(TPB)
k_bin(const float2* __restrict__ c2)
{
    const int gi = blockIdx.x * TPB + threadIdx.x;   // 0..8191

    if (gi < NCELL) g_bcnt[gi] = 0;
    if (gi == NCELL) g_ovfcnt = 0;

    // grid barrier over 32 trivially co-resident CTAs (replay-safe reset)
    __syncthreads();
    if (threadIdx.x == 0) {
        __threadfence();
        atomicAdd((int*)&g_arr, 1);
        while (g_arr != BIN_CTAS) __nanosleep(32);
        int p = atomicAdd(&g_dep, 1);
        if (p == BIN_CTAS - 1) {
            g_dep = 0;
            __threadfence();
            *(int*)&g_arr = 0;
        }
    }
    __syncthreads();

    float2 c = __ldg(&c2[gi]);
    const int cell = clamp_cell(c.y) * G + clamp_cell(c.x);
    float sc = __fadd_rn(__fmul_rn(c.x, c.x), __fmul_rn(c.y, c.y));
    float4 p = make_float4(c.x, c.y, sc, __int_as_float(gi));

    int pos = atomicAdd(&g_bcnt[cell], 1);
    if (pos < CAP) g_pts[cell * CAP + pos] = p;
    else           g_ovf[atomicAdd(&g_ovfcnt, 1)] = p;   // capacity N_PTS: safe
}

// ---------------------------------------------------------------------------
// Warp-collective exact NN for one query. Returns winning point index.
// Exact per-pair semantics (verified bit-identical to reference):
//   m = fma(a1, py, RN(a0*px));  d = fma(m, -2, RN(sa+sc))
// Lexicographic (ordered-d, idx) min == jnp.argmin first occurrence.
// ---------------------------------------------------------------------------
__device__ __forceinline__ int warp_nn(float a0, float a1, float sa, int lane)
{
    const float sa_ = sa;
    const int cx = clamp_cell(a0);
    const int cy = clamp_cell(a1);

    // query clearance to the point domain [0,1] per axis
    const float dxo = fmaxf(fmaxf(a0 - 1.0f, -a0), 0.0f);
    const float dyo = fmaxf(fmaxf(a1 - 1.0f, -a1), 0.0f);
    const float dxo2 = dxo * dxo;
    const float dyo2 = dyo * dyo;

    u64 bestk = ~0ull;

    #define EVAL_PT(P) do {                                                  \
        float m_ = __fmaf_rn(a1, (P).y, __fmul_rn(a0, (P).x));               \
        float d_ = __fmaf_rn(m_, -2.0f, __fadd_rn(sa_, (P).z));              \
        u32 ub_ = __float_as_uint(d_);                                       \
        ub_ = (ub_ & 0x80000000u) ? ~ub_ : (ub_ | 0x80000000u);              \
        u64 key_ = ((u64)ub_ << 32) | (u32)__float_as_uint((P).w);           \
        bestk = (key_ < bestk) ? key_ : bestk;                               \
    } while (0)

    int r = 1;
    while (true) {
        const int x0 = max(cx - r, 0), x1 = min(cx + r, G - 1);
        const int y0 = max(cy - r, 0), y1 = min(cy + r, G - 1);
        const int w = x1 - x0 + 1;
        const int ncell = w * (y1 - y0 + 1);
        const u32 mgc = (1u << 20) / (u32)w + 1u;   // exact div magic, cl<4096

        for (int base = 0; base < ncell; base += 32) {
            const int cl = base + lane;
            int s = 0, cnt = 0;
            if (cl < ncell) {
                int yy = (int)(((u64)(u32)cl * mgc) >> 20);
                int xx = cl - yy * w;
                int cell = (y0 + yy) * G + x0 + xx;
                cnt = min(__ldg(&g_bcnt[cell]), CAP);
                s = cell * CAP;
            }
            // warp exclusive scan of counts
            int inc = cnt;
            #pragma unroll
            for (int o = 1; o < 32; o <<= 1) {
                int n = __shfl_up_sync(FULL, inc, o);
                if (lane >= o) inc += n;
            }
            const int excl  = inc - cnt;
            const int total = __shfl_sync(FULL, inc, 31);

            for (int t0 = 0; t0 < total; t0 += 32) {
                const int t = t0 + lane;
                // 5-step warp binary search: largest j with excl[j] <= t
                int j = 0;
                #pragma unroll
                for (int st = 16; st; st >>= 1) {
                    int cd = j + st;
                    int ec = __shfl_sync(FULL, excl, cd);
                    if (ec <= t) j = cd;
                }
                int sj = __shfl_sync(FULL, s, j);
                int ej = __shfl_sync(FULL, excl, j);
                if (t < total) {
                    float4 p = __ldg(&g_pts[sj + (t - ej)]);
                    EVAL_PT(p);
                }
            }
        }

        // lb^2 to the unscanned region: per side-slab, (axis gap)^2 +
        // (query clearance to [0,1] in the other axis)^2.
        float lb2 = __int_as_float(0x7f800000);
        if (x0 > 0) {
            float dx = fmaxf(__fsub_rn(a0, (float)x0 * HC), 0.0f);
            lb2 = fminf(lb2, __fmaf_rn(dx, dx, dyo2));
        }
        if (x1 < G - 1) {
            float dx = fmaxf(__fsub_rn((float)(x1 + 1) * HC, a0), 0.0f);
            lb2 = fminf(lb2, __fmaf_rn(dx, dx, dyo2));
        }
        if (y0 > 0) {
            float dy = fmaxf(__fsub_rn(a1, (float)y0 * HC), 0.0f);
            lb2 = fminf(lb2, __fmaf_rn(dy, dy, dxo2));
        }
        if (y1 < G - 1) {
            float dy = fmaxf(__fsub_rn((float)(y1 + 1) * HC, a1), 0.0f);
            lb2 = fminf(lb2, __fmaf_rn(dy, dy, dxo2));
        }

        if (lb2 > 1e18f) break;                 // whole grid scanned

        // warp-wide best-so-far distance; ~0 key means "nothing scanned yet"
        u32 mu = __reduce_min_sync(FULL, (u32)(bestk >> 32));
        float bd;
        if (mu == 0xffffffffu)      bd = __int_as_float(0x7f800000);
        else if (mu & 0x80000000u)  bd = __uint_as_float(mu & 0x7fffffffu);
        else                        bd = __uint_as_float(~mu);
        if (lb2 > bd + 1e-4f) break;            // margin >> fp slack (~1e-6)
        r = 2 * r + 1;
    }

    // overflow points (normally none) — superset scan is min-safe
    const int ovn = __ldg(&g_ovfcnt);
    for (int t = lane; t < ovn; t += 32) {
        float4 p = __ldg(&g_ovf[t]);
        EVAL_PT(p);
    }
    #undef EVAL_PT

    // final lexicographic (d, idx) warp reduction
    u32 bub = (u32)(bestk >> 32);
    u32 mu  = __reduce_min_sync(FULL, bub);
    u32 cnd = (bub == mu) ? (u32)bestk : 0xffffffffu;
    return (int)__reduce_min_sync(FULL, cnd);
}

// ---------------------------------------------------------------------------
// K_query: 16 queries per CTA (2 per warp) + distributed output copies +
// coalesced value-row gather (exactly 1 float4 per thread).
// ---------------------------------------------------------------------------
__global__ void __launch_bounds__(TPB)
k_query(const float2* __restrict__ c2,
        const float*  __restrict__ spacing,
        const float*  __restrict__ shift,
        const float4* __restrict__ val4,
        float*        __restrict__ out)
{
    __shared__ int widx[QPC];
    const int lane = threadIdx.x & 31;
    const int wid  = threadIdx.x >> 5;

    float s0  = __ldg(&spacing[0]), s1  = __ldg(&spacing[1]);
    float sh0 = __ldg(&shift[0]),   sh1 = __ldg(&shift[1]);

    // ---- distributed output copies (independent of binning results) ----
    if (threadIdx.x < ITEMS) {
        int item = blockIdx.x * ITEMS + threadIdx.x;
        if (item < N_PTS * C4) {
            reinterpret_cast<float4*>(out)[item] = __ldg(&val4[item]);
        } else if (item < NITEM) {
            int i = item - N_PTS * C4;
            float2 cc = __ldg(&c2[i]);
            float xs = __fadd_rn(cc.x, s0);
            float ys = __fadd_rn(cc.y, s1);
            float2* outc = reinterpret_cast<float2*>(out + VOFF);
            outc[i]             = cc;
            outc[N_PTS   + i]   = make_float2(xs,   ys);
            outc[2*N_PTS + i]   = make_float2(cc.x, ys);
            outc[3*N_PTS + i]   = make_float2(xs,   cc.y);
        }
    }

    // ---- 2 queries per warp, sequential ----
    #pragma unroll
    for (int k = 0; k < 2; k++) {
        const int q = blockIdx.x * QPC + wid * 2 + k;   // 0..24575
        const int g = q >> 13;
        const int i = q & (N_PTS - 1);

        float2 c = __ldg(&c2[i]);
        float nc0, nc1;
        if (g == 0)      { nc0 = __fadd_rn(c.x, s0); nc1 = __fadd_rn(c.y, s1); }
        else if (g == 1) { nc0 = c.x;                nc1 = __fadd_rn(c.y, s1); }
        else             { nc0 = __fadd_rn(c.x, s0); nc1 = c.y;                }

        const float a0 = __fsub_rn(nc0, sh0);
        const float a1 = __fsub_rn(nc1, sh1);
        const float sa = __fadd_rn(__fmul_rn(a0, a0), __fmul_rn(a1, a1));

        int win = warp_nn(a0, a1, sa, lane);
        if (lane == 0) widx[wid * 2 + k] = win;
    }
    __syncthreads();

    // ---- coalesced gather: 16 winner rows, 1 float4 per thread ----
    {
        int rr  = threadIdx.x >> 4;         // 0..15
        int ccx = threadIdx.x & (C4 - 1);   // 0..15
        int row = blockIdx.x * QPC + rr;
        reinterpret_cast<float4*>(out)[(size_t)(N_PTS + row) * C4 + ccx] =
            __ldg(&val4[(size_t)widx[rr] * C4 + ccx]);
    }
}

// ---------------------------------------------------------------------------
extern "C" void kernel_launch(void* const* d_in, const int* in_sizes, int n_in,
                              void* d_out, int out_size)
{
    const float4* val4    = (const float4*)d_in[0];
    const float2* c2      = (const float2*)d_in[1];
    const float*  spacing = (const float*) d_in[2];
    const float*  shift   = (const float*) d_in[3];
    float* out = (float*)d_out;

    k_bin<<<BIN_CTAS, TPB>>>(c2);
    k_query<<<QW_CTAS, TPB>>>(c2, spacing, shift, val4, out);
}